// round 1
// baseline (speedup 1.0000x reference)
#include <cuda_runtime.h>
#include <math.h>

// Problem constants
#define B_     16
#define S_     512
#define D_     768
#define H_     12
#define DH_    64
#define L_     12
#define FF_    3072
#define VOCAB_ 40990
#define BS_    (B_ * S_)     // 8192 rows
#define D3_    (3 * D_)      // 2304

// ---------------------------------------------------------------------------
// Scratch (static device globals: allocation-free, graph-capturable)
// ---------------------------------------------------------------------------
__device__ float g_qkv[(size_t)BS_ * D3_];   // 75.5 MB
__device__ float g_attn[(size_t)BS_ * D_];   // 25.2 MB
__device__ float g_r1[(size_t)BS_ * D_];
__device__ float g_n[(size_t)BS_ * D_];
__device__ float g_ff[(size_t)BS_ * FF_];    // 100.7 MB
__device__ float g_r2[(size_t)BS_ * D_];

// ---------------------------------------------------------------------------
// Embedding: out[t] = we[x[t,0]] + we[x[t,1]]
// Handles x stored as int32 or int64 (detected on device; deterministic).
// ---------------------------------------------------------------------------
__global__ void embed_kernel(const void* __restrict__ x,
                             const float* __restrict__ we,
                             float* __restrict__ out)
{
    __shared__ int is64;
    int t = blockIdx.x;
    if (threadIdx.x == 0) {
        // If data is really int64, every 8-byte word is a valid index < VOCAB.
        // If it's int32, the high half of almost every word is a random index
        // (nonzero with prob ~1-2.4e-5), so 64 consecutive zeros is impossible.
        const unsigned long long* p = (const unsigned long long*)x;
        int ok = 1;
        #pragma unroll 1
        for (int i = 0; i < 64; i++)
            if (p[i] >= (unsigned long long)VOCAB_) { ok = 0; break; }
        is64 = ok;
    }
    __syncthreads();

    long long i0, i1;
    if (is64) {
        const long long* p = (const long long*)x;
        i0 = p[2 * t]; i1 = p[2 * t + 1];
    } else {
        const int* p = (const int*)x;
        i0 = p[2 * t]; i1 = p[2 * t + 1];
    }
    const float* w0 = we + (size_t)i0 * D_;
    const float* w1 = we + (size_t)i1 * D_;
    float* o = out + (size_t)t * D_;
    for (int c = threadIdx.x; c < D_; c += blockDim.x)
        o[c] = w0[c] + w1[c];
}

// ---------------------------------------------------------------------------
// SGEMM: C[M,N] = A[M,K] @ B[K,N] (+bias) (+res) (gelu)
// 128x128x16 tile, 256 threads, 8x8 microtile. M%128==0, N%128==0, K%16==0.
// ---------------------------------------------------------------------------
template<bool BIAS, bool RES, bool DOGELU>
__global__ __launch_bounds__(256) void sgemm_kernel(
    const float* __restrict__ A, const float* __restrict__ Bm,
    const float* __restrict__ bias, const float* __restrict__ res,
    float* __restrict__ C, int M, int N, int K)
{
    const int BK = 16;
    __shared__ float As[BK][128 + 4];   // padded: conflict-free + 16B-aligned rows
    __shared__ float Bs[BK][128];

    int tid = threadIdx.x;
    int bm = blockIdx.y * 128, bn = blockIdx.x * 128;
    int tx = tid & 15, ty = tid >> 4;
    int row0 = ty * 8, col0 = tx * 8;

    float acc[8][8];
    #pragma unroll
    for (int i = 0; i < 8; i++)
        #pragma unroll
        for (int j = 0; j < 8; j++) acc[i][j] = 0.f;

    int aRow = tid >> 2;          // 0..63
    int aK   = (tid & 3) * 4;     // 0,4,8,12
    int bRow = tid >> 5;          // 0..7
    int bCol = (tid & 31) * 4;    // 0..124

    for (int k0 = 0; k0 < K; k0 += BK) {
        #pragma unroll
        for (int h = 0; h < 2; h++) {
            float4 v = *(const float4*)(A + (size_t)(bm + aRow + h * 64) * K + (k0 + aK));
            As[aK + 0][aRow + h * 64] = v.x;
            As[aK + 1][aRow + h * 64] = v.y;
            As[aK + 2][aRow + h * 64] = v.z;
            As[aK + 3][aRow + h * 64] = v.w;
        }
        #pragma unroll
        for (int h = 0; h < 2; h++) {
            *(float4*)&Bs[bRow + h * 8][bCol] =
                *(const float4*)(Bm + (size_t)(k0 + bRow + h * 8) * N + (bn + bCol));
        }
        __syncthreads();

        #pragma unroll
        for (int kk = 0; kk < BK; kk++) {
            float ra[8], rb[8];
            #pragma unroll
            for (int i = 0; i < 8; i++) ra[i] = As[kk][row0 + i];
            #pragma unroll
            for (int j = 0; j < 8; j++) rb[j] = Bs[kk][col0 + j];
            #pragma unroll
            for (int i = 0; i < 8; i++)
                #pragma unroll
                for (int j = 0; j < 8; j++) acc[i][j] += ra[i] * rb[j];
        }
        __syncthreads();
    }

    #pragma unroll
    for (int i = 0; i < 8; i++) {
        int r = bm + row0 + i;
        #pragma unroll
        for (int j = 0; j < 8; j++) {
            int c = bn + col0 + j;
            float v = acc[i][j];
            if (BIAS) v += bias[c];
            if (RES)  v += res[(size_t)r * N + c];
            if (DOGELU) {
                float u = v;
                float inner = 0.7978845608028654f * (u + 0.044715f * u * u * u);
                v = 0.5f * u * (1.0f + tanhf(inner));
            }
            C[(size_t)r * N + c] = v;
        }
    }
}

// ---------------------------------------------------------------------------
// Fused causal flash attention (fp32). One block per (q_tile=64, head, batch).
// TQ=64, TK=32. K-tile SMEM is reused as the P-tile (aliased, sync-guarded).
// ---------------------------------------------------------------------------
__global__ __launch_bounds__(256) void attn_kernel(const float* __restrict__ qkv,
                                                   float* __restrict__ out)
{
    const int TQ = 64, TK = 32, KS = DH_ + 1;  // KS: padded K row stride
    __shared__ float Qs[TQ][DH_];      // 16 KB
    __shared__ float KP[TK * KS];      // 8.3 KB : K tile, then reused as P[64][32]
    __shared__ float Vs[TK][DH_];      // 8 KB

    int tid = threadIdx.x;
    int qt = blockIdx.x, head = blockIdx.y, batch = blockIdx.z;
    int qbase = qt * TQ;
    const float* base = qkv + (size_t)batch * S_ * D3_;
    int hd = head * DH_;

    // Load Q tile (64x64 floats)
    #pragma unroll
    for (int t = 0; t < 4; t++) {
        int idx = tid + t * 256;
        int r = idx >> 4, d4 = (idx & 15) * 4;
        *(float4*)&Qs[r][d4] =
            *(const float4*)(base + (size_t)(qbase + r) * D3_ + hd + d4);
    }

    int tx = tid & 15, ty = tid >> 4;
    int r0 = ty * 4;       // this thread's 4 query rows (S and PV phases agree)
    int k0 = tx * 2;       // 2 key columns in S phase
    int d0 = tx * 4;       // 4 output dims in PV phase

    float acc[4][4];
    float mrow[4], lrow[4];
    #pragma unroll
    for (int i = 0; i < 4; i++) {
        mrow[i] = -1e30f; lrow[i] = 0.f;
        #pragma unroll
        for (int j = 0; j < 4; j++) acc[i][j] = 0.f;
    }

    int ntiles = 2 * (qt + 1);  // causal: only k <= qbase+63
    for (int kt = 0; kt < ntiles; kt++) {
        int kbase = kt * TK;
        __syncthreads();  // prior P/V reads (and Q loads on iter 0) complete

        // Load K (32x64, padded stride) and V (32x64)
        #pragma unroll
        for (int t = 0; t < 2; t++) {
            int idx = tid + t * 256;
            int k = idx >> 4, d4 = (idx & 15) * 4;
            float4 kv = *(const float4*)(base + (size_t)(kbase + k) * D3_ + D_ + hd + d4);
            KP[k * KS + d4 + 0] = kv.x;
            KP[k * KS + d4 + 1] = kv.y;
            KP[k * KS + d4 + 2] = kv.z;
            KP[k * KS + d4 + 3] = kv.w;
            *(float4*)&Vs[k][d4] =
                *(const float4*)(base + (size_t)(kbase + k) * D3_ + 2 * D_ + hd + d4);
        }
        __syncthreads();

        // S = Q K^T : s[4 rows][2 keys]
        float s[4][2] = {{0.f,0.f},{0.f,0.f},{0.f,0.f},{0.f,0.f}};
        #pragma unroll 8
        for (int d = 0; d < DH_; d++) {
            float kv0 = KP[(k0 + 0) * KS + d];
            float kv1 = KP[(k0 + 1) * KS + d];
            #pragma unroll
            for (int i = 0; i < 4; i++) {
                float qv = Qs[r0 + i][d];
                s[i][0] += qv * kv0;
                s[i][1] += qv * kv1;
            }
        }
        // scale + causal mask
        #pragma unroll
        for (int i = 0; i < 4; i++)
            #pragma unroll
            for (int j = 0; j < 2; j++) {
                int gq = qbase + r0 + i, gk = kbase + k0 + j;
                s[i][j] = (gk <= gq) ? s[i][j] * 0.125f : -1e30f;
            }

        // Online softmax stats. Each row's 32 scores live in one 16-lane group
        // (lanes with equal ty), so xor-shuffles 8,4,2,1 reduce exactly the row.
        float mnew[4], alpha[4];
        #pragma unroll
        for (int i = 0; i < 4; i++) {
            float mx = fmaxf(s[i][0], s[i][1]);
            #pragma unroll
            for (int o = 8; o > 0; o >>= 1)
                mx = fmaxf(mx, __shfl_xor_sync(0xffffffffu, mx, o));
            mnew[i]  = fmaxf(mrow[i], mx);
            alpha[i] = expf(mrow[i] - mnew[i]);   // 0 on first tile (mrow=-1e30)
            mrow[i]  = mnew[i];
        }
        __syncthreads();  // all K reads done -> safe to overwrite KP with P

        #pragma unroll
        for (int i = 0; i < 4; i++) {
            float p0 = expf(s[i][0] - mnew[i]);
            float p1 = expf(s[i][1] - mnew[i]);
            KP[(r0 + i) * TK + k0 + 0] = p0;
            KP[(r0 + i) * TK + k0 + 1] = p1;
            float sum = p0 + p1;
            #pragma unroll
            for (int o = 8; o > 0; o >>= 1)
                sum += __shfl_xor_sync(0xffffffffu, sum, o);
            lrow[i] = lrow[i] * alpha[i] + sum;
            #pragma unroll
            for (int j = 0; j < 4; j++) acc[i][j] *= alpha[i];
        }
        __syncthreads();  // P visible to all

        // O += P @ V
        #pragma unroll 4
        for (int k = 0; k < TK; k++) {
            float4 v = *(const float4*)&Vs[k][d0];
            #pragma unroll
            for (int i = 0; i < 4; i++) {
                float p = KP[(r0 + i) * TK + k];
                acc[i][0] += p * v.x;
                acc[i][1] += p * v.y;
                acc[i][2] += p * v.z;
                acc[i][3] += p * v.w;
            }
        }
    }

    // Normalize and store into [B*S, D] layout
    #pragma unroll
    for (int i = 0; i < 4; i++) {
        float inv = 1.0f / lrow[i];
        float4 o;
        o.x = acc[i][0] * inv; o.y = acc[i][1] * inv;
        o.z = acc[i][2] * inv; o.w = acc[i][3] * inv;
        *(float4*)(out + (size_t)(batch * S_ + qbase + r0 + i) * D_ + hd + d0) = o;
    }
}

// ---------------------------------------------------------------------------
// LayerNorm over D=768 per row; 256 threads, 3 elements each.
// ---------------------------------------------------------------------------
__global__ __launch_bounds__(256) void ln_kernel(const float* __restrict__ x,
                                                 const float* __restrict__ g,
                                                 const float* __restrict__ b,
                                                 float* __restrict__ out)
{
    int row = blockIdx.x;
    int tid = threadIdx.x;
    const float* xr = x + (size_t)row * D_;
    float v0 = xr[tid], v1 = xr[tid + 256], v2 = xr[tid + 512];

    __shared__ float red[8];
    float s = v0 + v1 + v2;
    #pragma unroll
    for (int o = 16; o > 0; o >>= 1) s += __shfl_xor_sync(~0u, s, o);
    if ((tid & 31) == 0) red[tid >> 5] = s;
    __syncthreads();
    float tot = 0.f;
    if (tid < 32) {
        tot = (tid < 8) ? red[tid] : 0.f;
        #pragma unroll
        for (int o = 4; o > 0; o >>= 1) tot += __shfl_xor_sync(~0u, tot, o);
        if (tid == 0) red[0] = tot;
    }
    __syncthreads();
    float mean = red[0] * (1.0f / D_);

    float d0 = v0 - mean, d1 = v1 - mean, d2 = v2 - mean;
    float q = d0 * d0 + d1 * d1 + d2 * d2;
    #pragma unroll
    for (int o = 16; o > 0; o >>= 1) q += __shfl_xor_sync(~0u, q, o);
    __syncthreads();  // protect red[] reuse (everyone has read mean)
    if ((tid & 31) == 0) red[tid >> 5] = q;
    __syncthreads();
    if (tid < 32) {
        float t = (tid < 8) ? red[tid] : 0.f;
        #pragma unroll
        for (int o = 4; o > 0; o >>= 1) t += __shfl_xor_sync(~0u, t, o);
        if (tid == 0) red[0] = t;
    }
    __syncthreads();
    float rstd = rsqrtf(red[0] * (1.0f / D_) + 1e-5f);

    float* o = out + (size_t)row * D_;
    o[tid]       = d0 * rstd * g[tid]       + b[tid];
    o[tid + 256] = d1 * rstd * g[tid + 256] + b[tid + 256];
    o[tid + 512] = d2 * rstd * g[tid + 512] + b[tid + 512];
}

// ---------------------------------------------------------------------------
// Launch
// ---------------------------------------------------------------------------
extern "C" void kernel_launch(void* const* d_in, const int* in_sizes, int n_in,
                              void* d_out, int out_size)
{
    (void)in_sizes; (void)n_in; (void)out_size;

    const void*  x           = d_in[0];
    const float* we          = (const float*)d_in[1];
    const float* c_attn_w    = (const float*)d_in[2];
    const float* c_attn_b    = (const float*)d_in[3];
    const float* attn_proj_w = (const float*)d_in[4];
    const float* attn_proj_b = (const float*)d_in[5];
    const float* ln1_g       = (const float*)d_in[6];
    const float* ln1_b       = (const float*)d_in[7];
    const float* fc_w        = (const float*)d_in[8];
    const float* fc_b        = (const float*)d_in[9];
    const float* mlp_proj_w  = (const float*)d_in[10];
    const float* mlp_proj_b  = (const float*)d_in[11];
    const float* ln2_g       = (const float*)d_in[12];
    const float* ln2_b       = (const float*)d_in[13];
    float* out = (float*)d_out;

    float *qkv, *attnb, *r1, *nbuf, *ff, *r2;
    cudaGetSymbolAddress((void**)&qkv,   g_qkv);
    cudaGetSymbolAddress((void**)&attnb, g_attn);
    cudaGetSymbolAddress((void**)&r1,    g_r1);
    cudaGetSymbolAddress((void**)&nbuf,  g_n);
    cudaGetSymbolAddress((void**)&ff,    g_ff);
    cudaGetSymbolAddress((void**)&r2,    g_r2);

    // h0 = we[x].sum(axis=2) -> out slice 0 (also layer-0 input)
    embed_kernel<<<BS_, 256>>>(x, we, out);

    for (int l = 0; l < L_; l++) {
        const float* h    = out + (size_t)l * BS_ * D_;
        float*       hout = out + (size_t)(l + 1) * BS_ * D_;

        // qkv = h @ caw + cab
        sgemm_kernel<true, false, false><<<dim3(D3_ / 128, BS_ / 128), 256>>>(
            h, c_attn_w + (size_t)l * D_ * D3_, c_attn_b + (size_t)l * D3_,
            nullptr, qkv, BS_, D3_, D_);

        // a = causal_attention(qkv)
        attn_kernel<<<dim3(S_ / 64, H_, B_), 256>>>(qkv, attnb);

        // r1 = a @ apw + apb + h
        sgemm_kernel<true, true, false><<<dim3(D_ / 128, BS_ / 128), 256>>>(
            attnb, attn_proj_w + (size_t)l * D_ * D_, attn_proj_b + (size_t)l * D_,
            h, r1, BS_, D_, D_);

        // n = LN(r1)
        ln_kernel<<<BS_, 256>>>(r1, ln1_g + (size_t)l * D_, ln1_b + (size_t)l * D_, nbuf);

        // ff = gelu(n @ fw + fb)
        sgemm_kernel<true, false, true><<<dim3(FF_ / 128, BS_ / 128), 256>>>(
            nbuf, fc_w + (size_t)l * D_ * FF_, fc_b + (size_t)l * FF_,
            nullptr, ff, BS_, FF_, D_);

        // r2 = ff @ pw + pb + n
        sgemm_kernel<true, true, false><<<dim3(D_ / 128, BS_ / 128), 256>>>(
            ff, mlp_proj_w + (size_t)l * FF_ * D_, mlp_proj_b + (size_t)l * D_,
            nbuf, r2, BS_, FF_ /*K*/ == FF_ ? D_ : D_, FF_);

        // out_{l+1} = LN(r2)  (also next layer's input)
        ln_kernel<<<BS_, 256>>>(r2, ln2_g + (size_t)l * D_, ln2_b + (size_t)l * D_, hout);
    }
}

// round 2
// speedup vs baseline: 2.2999x; 2.2999x over previous
#include <cuda_runtime.h>
#include <math.h>

// Problem constants
#define B_     16
#define S_     512
#define D_     768
#define H_     12
#define DH_    64
#define L_     12
#define FF_    3072
#define VOCAB_ 40990
#define BS_    (B_ * S_)     // 8192 rows
#define D3_    (3 * D_)      // 2304

// ---------------------------------------------------------------------------
// Scratch (static device globals: allocation-free, graph-capturable)
// ---------------------------------------------------------------------------
__device__ float g_qkv[(size_t)BS_ * D3_];   // 75.5 MB
__device__ float g_attn[(size_t)BS_ * D_];   // 25.2 MB
__device__ float g_r1[(size_t)BS_ * D_];
__device__ float g_n[(size_t)BS_ * D_];
__device__ float g_ff[(size_t)BS_ * FF_];    // 100.7 MB
__device__ float g_r2[(size_t)BS_ * D_];

// ---------------------------------------------------------------------------
// Embedding: out[t] = we[x[t,0]] + we[x[t,1]]  (x int32 or int64, detected)
// ---------------------------------------------------------------------------
__global__ void embed_kernel(const void* __restrict__ x,
                             const float* __restrict__ we,
                             float* __restrict__ out)
{
    __shared__ int is64;
    int t = blockIdx.x;
    if (threadIdx.x == 0) {
        const unsigned long long* p = (const unsigned long long*)x;
        int ok = 1;
        #pragma unroll 1
        for (int i = 0; i < 64; i++)
            if (p[i] >= (unsigned long long)VOCAB_) { ok = 0; break; }
        is64 = ok;
    }
    __syncthreads();

    long long i0, i1;
    if (is64) {
        const long long* p = (const long long*)x;
        i0 = p[2 * t]; i1 = p[2 * t + 1];
    } else {
        const int* p = (const int*)x;
        i0 = p[2 * t]; i1 = p[2 * t + 1];
    }
    const float* w0 = we + (size_t)i0 * D_;
    const float* w1 = we + (size_t)i1 * D_;
    float* o = out + (size_t)t * D_;
    for (int c = threadIdx.x; c < D_; c += blockDim.x)
        o[c] = w0[c] + w1[c];
}

// ---------------------------------------------------------------------------
// TF32 tensor-core GEMM: C[M,N] = A[M,K] @ B[K,N] (+bias)(+res)(gelu)
// Tile 128x128x32, 256 threads (8 warps), warp tile 32x64.
// mma.sync.aligned.m16n8k8 tf32, fp32 accumulate.
// Requirements: M%128==0, N%128==0, K%32==0, 16B-aligned pointers.
// ---------------------------------------------------------------------------
__device__ __forceinline__ unsigned f2tf(float f) {
    unsigned r;
    asm("cvt.rna.tf32.f32 %0, %1;" : "=r"(r) : "f"(f));
    return r;
}

__device__ __forceinline__ void mma_tf32(float c[4], const unsigned a[4],
                                         const unsigned b[2]) {
    asm volatile(
        "mma.sync.aligned.m16n8k8.row.col.f32.tf32.tf32.f32 "
        "{%0,%1,%2,%3},{%4,%5,%6,%7},{%8,%9},{%0,%1,%2,%3};"
        : "+f"(c[0]), "+f"(c[1]), "+f"(c[2]), "+f"(c[3])
        : "r"(a[0]), "r"(a[1]), "r"(a[2]), "r"(a[3]), "r"(b[0]), "r"(b[1]));
}

template<bool BIAS, bool RES, bool DOGELU>
__global__ __launch_bounds__(256) void mma_gemm_kernel(
    const float* __restrict__ A, const float* __restrict__ Bm,
    const float* __restrict__ bias, const float* __restrict__ res,
    float* __restrict__ C, int M, int N, int K)
{
    const int BK = 32;
    const int AST = BK + 4;    // 36: A row stride (conflict-free frag loads)
    const int BST = 128 + 8;   // 136: B row stride (conflict-free frag loads)
    __shared__ unsigned As[128 * AST];  // [m][k], tf32 bits
    __shared__ unsigned Bs[BK * BST];   // [k][n], tf32 bits

    const int tid  = threadIdx.x;
    const int lane = tid & 31;
    const int wid  = tid >> 5;
    const int gid  = lane >> 2;   // groupID 0..7
    const int tig  = lane & 3;    // thread-in-group 0..3
    const int warp_m = wid >> 1;  // 0..3 -> 32-row slab
    const int warp_n = wid & 1;   // 0..1 -> 64-col slab

    const int bm = blockIdx.y * 128, bn = blockIdx.x * 128;

    float acc[2][8][4];
    #pragma unroll
    for (int i = 0; i < 2; i++)
        #pragma unroll
        for (int j = 0; j < 8; j++)
            #pragma unroll
            for (int c = 0; c < 4; c++) acc[i][j][c] = 0.f;

    // Fill indices
    const int aRow = tid >> 3;        // 0..31 (pass adds h*32)
    const int aK   = (tid & 7) * 4;   // 0..28
    const int bRow = tid >> 5;        // 0..7  (pass adds h*8)
    const int bCol = (tid & 31) * 4;  // 0..124

    for (int k0 = 0; k0 < K; k0 += BK) {
        // A tile: [128 rows][32 k], row-major, vectorized fill
        #pragma unroll
        for (int h = 0; h < 4; h++) {
            int r = h * 32 + aRow;
            float4 v = *(const float4*)(A + (size_t)(bm + r) * K + (k0 + aK));
            unsigned4_fill: ;
            uint4 u;
            u.x = f2tf(v.x); u.y = f2tf(v.y); u.z = f2tf(v.z); u.w = f2tf(v.w);
            *(uint4*)&As[r * AST + aK] = u;
        }
        // B tile: [32 k][128 n]
        #pragma unroll
        for (int h = 0; h < 4; h++) {
            int r = h * 8 + bRow;
            float4 v = *(const float4*)(Bm + (size_t)(k0 + r) * N + (bn + bCol));
            uint4 u;
            u.x = f2tf(v.x); u.y = f2tf(v.y); u.z = f2tf(v.z); u.w = f2tf(v.w);
            *(uint4*)&Bs[r * BST + bCol] = u;
        }
        __syncthreads();

        #pragma unroll
        for (int ks = 0; ks < 4; ks++) {
            const int k8 = ks * 8;
            unsigned a[2][4], b[8][2];
            #pragma unroll
            for (int im = 0; im < 2; im++) {
                int m0 = warp_m * 32 + im * 16;
                a[im][0] = As[(m0 + gid)     * AST + k8 + tig];
                a[im][1] = As[(m0 + gid + 8) * AST + k8 + tig];
                a[im][2] = As[(m0 + gid)     * AST + k8 + tig + 4];
                a[im][3] = As[(m0 + gid + 8) * AST + k8 + tig + 4];
            }
            #pragma unroll
            for (int in_ = 0; in_ < 8; in_++) {
                int c0 = warp_n * 64 + in_ * 8 + gid;
                b[in_][0] = Bs[(k8 + tig)     * BST + c0];
                b[in_][1] = Bs[(k8 + tig + 4) * BST + c0];
            }
            #pragma unroll
            for (int im = 0; im < 2; im++)
                #pragma unroll
                for (int in_ = 0; in_ < 8; in_++)
                    mma_tf32(acc[im][in_], a[im], b[in_]);
        }
        __syncthreads();
    }

    // Epilogue: c0,c1 -> (row, col..col+1); c2,c3 -> (row+8, col..col+1)
    #pragma unroll
    for (int im = 0; im < 2; im++) {
        #pragma unroll
        for (int in_ = 0; in_ < 8; in_++) {
            int r = bm + warp_m * 32 + im * 16 + gid;
            int c = bn + warp_n * 64 + in_ * 8 + tig * 2;
            #pragma unroll
            for (int half = 0; half < 2; half++) {
                int rr = r + half * 8;
                float v0 = acc[im][in_][half * 2 + 0];
                float v1 = acc[im][in_][half * 2 + 1];
                if (BIAS) { v0 += bias[c]; v1 += bias[c + 1]; }
                if (RES) {
                    const float* rp = res + (size_t)rr * N + c;
                    v0 += rp[0]; v1 += rp[1];
                }
                if (DOGELU) {
                    float i0 = 0.7978845608028654f * (v0 + 0.044715f * v0 * v0 * v0);
                    float i1 = 0.7978845608028654f * (v1 + 0.044715f * v1 * v1 * v1);
                    v0 = 0.5f * v0 * (1.0f + tanhf(i0));
                    v1 = 0.5f * v1 * (1.0f + tanhf(i1));
                }
                *(float2*)(C + (size_t)rr * N + c) = make_float2(v0, v1);
            }
        }
    }
}

// ---------------------------------------------------------------------------
// Fused causal flash attention (fp32) — unchanged from passing round.
// ---------------------------------------------------------------------------
__global__ __launch_bounds__(256) void attn_kernel(const float* __restrict__ qkv,
                                                   float* __restrict__ out)
{
    const int TQ = 64, TK = 32, KS = DH_ + 1;
    __shared__ float Qs[TQ][DH_];
    __shared__ float KP[TK * KS];
    __shared__ float Vs[TK][DH_];

    int tid = threadIdx.x;
    int qt = blockIdx.x, head = blockIdx.y, batch = blockIdx.z;
    int qbase = qt * TQ;
    const float* base = qkv + (size_t)batch * S_ * D3_;
    int hd = head * DH_;

    #pragma unroll
    for (int t = 0; t < 4; t++) {
        int idx = tid + t * 256;
        int r = idx >> 4, d4 = (idx & 15) * 4;
        *(float4*)&Qs[r][d4] =
            *(const float4*)(base + (size_t)(qbase + r) * D3_ + hd + d4);
    }

    int tx = tid & 15, ty = tid >> 4;
    int r0 = ty * 4;
    int k0 = tx * 2;
    int d0 = tx * 4;

    float acc[4][4];
    float mrow[4], lrow[4];
    #pragma unroll
    for (int i = 0; i < 4; i++) {
        mrow[i] = -1e30f; lrow[i] = 0.f;
        #pragma unroll
        for (int j = 0; j < 4; j++) acc[i][j] = 0.f;
    }

    int ntiles = 2 * (qt + 1);
    for (int kt = 0; kt < ntiles; kt++) {
        int kbase = kt * TK;
        __syncthreads();

        #pragma unroll
        for (int t = 0; t < 2; t++) {
            int idx = tid + t * 256;
            int k = idx >> 4, d4 = (idx & 15) * 4;
            float4 kv = *(const float4*)(base + (size_t)(kbase + k) * D3_ + D_ + hd + d4);
            KP[k * KS + d4 + 0] = kv.x;
            KP[k * KS + d4 + 1] = kv.y;
            KP[k * KS + d4 + 2] = kv.z;
            KP[k * KS + d4 + 3] = kv.w;
            *(float4*)&Vs[k][d4] =
                *(const float4*)(base + (size_t)(kbase + k) * D3_ + 2 * D_ + hd + d4);
        }
        __syncthreads();

        float s[4][2] = {{0.f,0.f},{0.f,0.f},{0.f,0.f},{0.f,0.f}};
        #pragma unroll 8
        for (int d = 0; d < DH_; d++) {
            float kv0 = KP[(k0 + 0) * KS + d];
            float kv1 = KP[(k0 + 1) * KS + d];
            #pragma unroll
            for (int i = 0; i < 4; i++) {
                float qv = Qs[r0 + i][d];
                s[i][0] += qv * kv0;
                s[i][1] += qv * kv1;
            }
        }
        #pragma unroll
        for (int i = 0; i < 4; i++)
            #pragma unroll
            for (int j = 0; j < 2; j++) {
                int gq = qbase + r0 + i, gk = kbase + k0 + j;
                s[i][j] = (gk <= gq) ? s[i][j] * 0.125f : -1e30f;
            }

        float mnew[4], alpha[4];
        #pragma unroll
        for (int i = 0; i < 4; i++) {
            float mx = fmaxf(s[i][0], s[i][1]);
            #pragma unroll
            for (int o = 8; o > 0; o >>= 1)
                mx = fmaxf(mx, __shfl_xor_sync(0xffffffffu, mx, o));
            mnew[i]  = fmaxf(mrow[i], mx);
            alpha[i] = expf(mrow[i] - mnew[i]);
            mrow[i]  = mnew[i];
        }
        __syncthreads();

        #pragma unroll
        for (int i = 0; i < 4; i++) {
            float p0 = expf(s[i][0] - mnew[i]);
            float p1 = expf(s[i][1] - mnew[i]);
            KP[(r0 + i) * TK + k0 + 0] = p0;
            KP[(r0 + i) * TK + k0 + 1] = p1;
            float sum = p0 + p1;
            #pragma unroll
            for (int o = 8; o > 0; o >>= 1)
                sum += __shfl_xor_sync(0xffffffffu, sum, o);
            lrow[i] = lrow[i] * alpha[i] + sum;
            #pragma unroll
            for (int j = 0; j < 4; j++) acc[i][j] *= alpha[i];
        }
        __syncthreads();

        #pragma unroll 4
        for (int k = 0; k < TK; k++) {
            float4 v = *(const float4*)&Vs[k][d0];
            #pragma unroll
            for (int i = 0; i < 4; i++) {
                float p = KP[(r0 + i) * TK + k];
                acc[i][0] += p * v.x;
                acc[i][1] += p * v.y;
                acc[i][2] += p * v.z;
                acc[i][3] += p * v.w;
            }
        }
    }

    #pragma unroll
    for (int i = 0; i < 4; i++) {
        float inv = 1.0f / lrow[i];
        float4 o;
        o.x = acc[i][0] * inv; o.y = acc[i][1] * inv;
        o.z = acc[i][2] * inv; o.w = acc[i][3] * inv;
        *(float4*)(out + (size_t)(batch * S_ + qbase + r0 + i) * D_ + hd + d0) = o;
    }
}

// ---------------------------------------------------------------------------
// LayerNorm over D=768 per row; 256 threads, 3 elements each. (unchanged)
// ---------------------------------------------------------------------------
__global__ __launch_bounds__(256) void ln_kernel(const float* __restrict__ x,
                                                 const float* __restrict__ g,
                                                 const float* __restrict__ b,
                                                 float* __restrict__ out)
{
    int row = blockIdx.x;
    int tid = threadIdx.x;
    const float* xr = x + (size_t)row * D_;
    float v0 = xr[tid], v1 = xr[tid + 256], v2 = xr[tid + 512];

    __shared__ float red[8];
    float s = v0 + v1 + v2;
    #pragma unroll
    for (int o = 16; o > 0; o >>= 1) s += __shfl_xor_sync(~0u, s, o);
    if ((tid & 31) == 0) red[tid >> 5] = s;
    __syncthreads();
    float tot = 0.f;
    if (tid < 32) {
        tot = (tid < 8) ? red[tid] : 0.f;
        #pragma unroll
        for (int o = 4; o > 0; o >>= 1) tot += __shfl_xor_sync(~0u, tot, o);
        if (tid == 0) red[0] = tot;
    }
    __syncthreads();
    float mean = red[0] * (1.0f / D_);

    float d0 = v0 - mean, d1 = v1 - mean, d2 = v2 - mean;
    float q = d0 * d0 + d1 * d1 + d2 * d2;
    #pragma unroll
    for (int o = 16; o > 0; o >>= 1) q += __shfl_xor_sync(~0u, q, o);
    __syncthreads();
    if ((tid & 31) == 0) red[tid >> 5] = q;
    __syncthreads();
    if (tid < 32) {
        float t = (tid < 8) ? red[tid] : 0.f;
        #pragma unroll
        for (int o = 4; o > 0; o >>= 1) t += __shfl_xor_sync(~0u, t, o);
        if (tid == 0) red[0] = t;
    }
    __syncthreads();
    float rstd = rsqrtf(red[0] * (1.0f / D_) + 1e-5f);

    float* o = out + (size_t)row * D_;
    o[tid]       = d0 * rstd * g[tid]       + b[tid];
    o[tid + 256] = d1 * rstd * g[tid + 256] + b[tid + 256];
    o[tid + 512] = d2 * rstd * g[tid + 512] + b[tid + 512];
}

// ---------------------------------------------------------------------------
// Launch
// ---------------------------------------------------------------------------
extern "C" void kernel_launch(void* const* d_in, const int* in_sizes, int n_in,
                              void* d_out, int out_size)
{
    (void)in_sizes; (void)n_in; (void)out_size;

    const void*  x           = d_in[0];
    const float* we          = (const float*)d_in[1];
    const float* c_attn_w    = (const float*)d_in[2];
    const float* c_attn_b    = (const float*)d_in[3];
    const float* attn_proj_w = (const float*)d_in[4];
    const float* attn_proj_b = (const float*)d_in[5];
    const float* ln1_g       = (const float*)d_in[6];
    const float* ln1_b       = (const float*)d_in[7];
    const float* fc_w        = (const float*)d_in[8];
    const float* fc_b        = (const float*)d_in[9];
    const float* mlp_proj_w  = (const float*)d_in[10];
    const float* mlp_proj_b  = (const float*)d_in[11];
    const float* ln2_g       = (const float*)d_in[12];
    const float* ln2_b       = (const float*)d_in[13];
    float* out = (float*)d_out;

    float *qkv, *attnb, *r1, *nbuf, *ff, *r2;
    cudaGetSymbolAddress((void**)&qkv,   g_qkv);
    cudaGetSymbolAddress((void**)&attnb, g_attn);
    cudaGetSymbolAddress((void**)&r1,    g_r1);
    cudaGetSymbolAddress((void**)&nbuf,  g_n);
    cudaGetSymbolAddress((void**)&ff,    g_ff);
    cudaGetSymbolAddress((void**)&r2,    g_r2);

    embed_kernel<<<BS_, 256>>>(x, we, out);

    for (int l = 0; l < L_; l++) {
        const float* h    = out + (size_t)l * BS_ * D_;
        float*       hout = out + (size_t)(l + 1) * BS_ * D_;

        // qkv = h @ caw + cab
        mma_gemm_kernel<true, false, false><<<dim3(D3_ / 128, BS_ / 128), 256>>>(
            h, c_attn_w + (size_t)l * D_ * D3_, c_attn_b + (size_t)l * D3_,
            nullptr, qkv, BS_, D3_, D_);

        // a = causal_attention(qkv)
        attn_kernel<<<dim3(S_ / 64, H_, B_), 256>>>(qkv, attnb);

        // r1 = a @ apw + apb + h
        mma_gemm_kernel<true, true, false><<<dim3(D_ / 128, BS_ / 128), 256>>>(
            attnb, attn_proj_w + (size_t)l * D_ * D_, attn_proj_b + (size_t)l * D_,
            h, r1, BS_, D_, D_);

        // n = LN(r1)
        ln_kernel<<<BS_, 256>>>(r1, ln1_g + (size_t)l * D_, ln1_b + (size_t)l * D_, nbuf);

        // ff = gelu(n @ fw + fb)
        mma_gemm_kernel<true, false, true><<<dim3(FF_ / 128, BS_ / 128), 256>>>(
            nbuf, fc_w + (size_t)l * D_ * FF_, fc_b + (size_t)l * FF_,
            nullptr, ff, BS_, FF_, D_);

        // r2 = ff @ pw + pb + n
        mma_gemm_kernel<true, true, false><<<dim3(D_ / 128, BS_ / 128), 256>>>(
            ff, mlp_proj_w + (size_t)l * FF_ * D_, mlp_proj_b + (size_t)l * D_,
            nbuf, r2, BS_, D_, FF_);

        // out_{l+1} = LN(r2)
        ln_kernel<<<BS_, 256>>>(r2, ln2_g + (size_t)l * D_, ln2_b + (size_t)l * D_, hout);
    }
}

// round 3
// speedup vs baseline: 2.6505x; 1.1525x over previous
#include <cuda_runtime.h>
#include <math.h>

// Problem constants
#define B_     16
#define S_     512
#define D_     768
#define H_     12
#define DH_    64
#define L_     12
#define FF_    3072
#define VOCAB_ 40990
#define BS_    (B_ * S_)     // 8192 rows
#define D3_    (3 * D_)      // 2304

// ---------------------------------------------------------------------------
// Scratch (static device globals: allocation-free, graph-capturable)
// ---------------------------------------------------------------------------
__device__ float g_qkv[(size_t)BS_ * D3_];   // 75.5 MB
__device__ float g_attn[(size_t)BS_ * D_];   // 25.2 MB
__device__ float g_r1[(size_t)BS_ * D_];
__device__ float g_n[(size_t)BS_ * D_];
__device__ float g_ff[(size_t)BS_ * FF_];    // 100.7 MB
__device__ float g_r2[(size_t)BS_ * D_];

// ---------------------------------------------------------------------------
// Embedding: out[t] = we[x[t,0]] + we[x[t,1]]  (x int32 or int64, detected)
// ---------------------------------------------------------------------------
__global__ void embed_kernel(const void* __restrict__ x,
                             const float* __restrict__ we,
                             float* __restrict__ out)
{
    __shared__ int is64;
    int t = blockIdx.x;
    if (threadIdx.x == 0) {
        const unsigned long long* p = (const unsigned long long*)x;
        int ok = 1;
        #pragma unroll 1
        for (int i = 0; i < 64; i++)
            if (p[i] >= (unsigned long long)VOCAB_) { ok = 0; break; }
        is64 = ok;
    }
    __syncthreads();

    long long i0, i1;
    if (is64) {
        const long long* p = (const long long*)x;
        i0 = p[2 * t]; i1 = p[2 * t + 1];
    } else {
        const int* p = (const int*)x;
        i0 = p[2 * t]; i1 = p[2 * t + 1];
    }
    const float* w0 = we + (size_t)i0 * D_;
    const float* w1 = we + (size_t)i1 * D_;
    float* o = out + (size_t)t * D_;
    for (int c = threadIdx.x; c < D_; c += blockDim.x)
        o[c] = w0[c] + w1[c];
}

// ---------------------------------------------------------------------------
// TF32 tensor-core GEMM with cp.async double-buffered pipeline.
// C[M,N] = A[M,K] @ B[K,N] (+bias)(+res)(gelu)
// Tile 128x128x32, 256 threads (8 warps), warp tile 32x64.
// Requirements: M%128==0, N%128==0, K%32==0, 16B-aligned pointers.
// ---------------------------------------------------------------------------
__device__ __forceinline__ unsigned f2tf(float f) {
    unsigned r;
    asm("cvt.rna.tf32.f32 %0, %1;" : "=r"(r) : "f"(f));
    return r;
}

__device__ __forceinline__ void mma_tf32(float c[4], const unsigned a[4],
                                         const unsigned b[2]) {
    asm volatile(
        "mma.sync.aligned.m16n8k8.row.col.f32.tf32.tf32.f32 "
        "{%0,%1,%2,%3},{%4,%5,%6,%7},{%8,%9},{%0,%1,%2,%3};"
        : "+f"(c[0]), "+f"(c[1]), "+f"(c[2]), "+f"(c[3])
        : "r"(a[0]), "r"(a[1]), "r"(a[2]), "r"(a[3]), "r"(b[0]), "r"(b[1]));
}

__device__ __forceinline__ void cp16(unsigned smem_addr, const float* gptr) {
    asm volatile("cp.async.cg.shared.global [%0], [%1], 16;\n"
                 :: "r"(smem_addr), "l"(gptr));
}

#define AST 36   // A row stride (floats): conflict-free, 144B = 16B-multiple
#define BST 136  // B row stride (floats): conflict-free, 544B = 16B-multiple
#define ASTAGE (128 * AST)
#define BSTAGE (32 * BST)
#define STAGEF (ASTAGE + BSTAGE)           // floats per stage
#define GEMM_SMEM_BYTES (2 * STAGEF * 4)   // 71680 bytes

template<bool BIAS, bool RES, bool DOGELU>
__global__ __launch_bounds__(256, 2) void mma_gemm_kernel(
    const float* __restrict__ A, const float* __restrict__ Bm,
    const float* __restrict__ bias, const float* __restrict__ res,
    float* __restrict__ C, int M, int N, int K)
{
    extern __shared__ float smem[];

    const int tid  = threadIdx.x;
    const int lane = tid & 31;
    const int wid  = tid >> 5;
    const int gid  = lane >> 2;   // 0..7
    const int tig  = lane & 3;    // 0..3
    const int warp_m = wid >> 1;  // 0..3 -> 32-row slab
    const int warp_n = wid & 1;   // 0..1 -> 64-col slab

    const int bm = blockIdx.y * 128, bn = blockIdx.x * 128;

    // Fill indices (16B vectors)
    const int aRow = tid >> 3;        // 0..31 (+h*32)
    const int aK   = (tid & 7) * 4;   // 0..28
    const int bRow = tid >> 5;        // 0..7  (+h*8)
    const int bCol = (tid & 31) * 4;  // 0..124

    const float* Abase = A + (size_t)bm * K;
    const float* Bbase = Bm + bn;

    // Issue cp.async for one k-chunk into stage s
    auto load_stage = [&](int s, int k0) {
        float* As = smem + s * STAGEF;
        float* Bs = As + ASTAGE;
        #pragma unroll
        for (int h = 0; h < 4; h++) {
            int r = h * 32 + aRow;
            cp16((unsigned)__cvta_generic_to_shared(&As[r * AST + aK]),
                 Abase + (size_t)r * K + (k0 + aK));
        }
        #pragma unroll
        for (int h = 0; h < 4; h++) {
            int r = h * 8 + bRow;
            cp16((unsigned)__cvta_generic_to_shared(&Bs[r * BST + bCol]),
                 Bbase + (size_t)(k0 + r) * N + bCol);
        }
        asm volatile("cp.async.commit_group;\n" ::: "memory");
    };

    float acc[2][8][4];
    #pragma unroll
    for (int i = 0; i < 2; i++)
        #pragma unroll
        for (int j = 0; j < 8; j++)
            #pragma unroll
            for (int c = 0; c < 4; c++) acc[i][j][c] = 0.f;

    const int NK = K >> 5;   // K/32 chunks
    load_stage(0, 0);

    for (int it = 0; it < NK; it++) {
        // Wait for chunk `it`; barrier also guarantees everyone finished
        // computing on the buffer we are about to overwrite.
        asm volatile("cp.async.wait_group 0;\n" ::: "memory");
        __syncthreads();
        if (it + 1 < NK) load_stage((it + 1) & 1, (it + 1) << 5);

        const float* As = smem + (it & 1) * STAGEF;
        const float* Bs = As + ASTAGE;

        #pragma unroll
        for (int ks = 0; ks < 4; ks++) {
            const int k8 = ks * 8;
            unsigned a[2][4], b[8][2];
            #pragma unroll
            for (int im = 0; im < 2; im++) {
                int m0 = warp_m * 32 + im * 16;
                a[im][0] = f2tf(As[(m0 + gid)     * AST + k8 + tig]);
                a[im][1] = f2tf(As[(m0 + gid + 8) * AST + k8 + tig]);
                a[im][2] = f2tf(As[(m0 + gid)     * AST + k8 + tig + 4]);
                a[im][3] = f2tf(As[(m0 + gid + 8) * AST + k8 + tig + 4]);
            }
            #pragma unroll
            for (int in_ = 0; in_ < 8; in_++) {
                int c0 = warp_n * 64 + in_ * 8 + gid;
                b[in_][0] = f2tf(Bs[(k8 + tig)     * BST + c0]);
                b[in_][1] = f2tf(Bs[(k8 + tig + 4) * BST + c0]);
            }
            #pragma unroll
            for (int im = 0; im < 2; im++)
                #pragma unroll
                for (int in_ = 0; in_ < 8; in_++)
                    mma_tf32(acc[im][in_], a[im], b[in_]);
        }
    }

    // Epilogue
    #pragma unroll
    for (int im = 0; im < 2; im++) {
        #pragma unroll
        for (int in_ = 0; in_ < 8; in_++) {
            int r = bm + warp_m * 32 + im * 16 + gid;
            int c = bn + warp_n * 64 + in_ * 8 + tig * 2;
            #pragma unroll
            for (int half = 0; half < 2; half++) {
                int rr = r + half * 8;
                float v0 = acc[im][in_][half * 2 + 0];
                float v1 = acc[im][in_][half * 2 + 1];
                if (BIAS) { v0 += bias[c]; v1 += bias[c + 1]; }
                if (RES) {
                    const float* rp = res + (size_t)rr * N + c;
                    v0 += rp[0]; v1 += rp[1];
                }
                if (DOGELU) {
                    float i0 = 0.7978845608028654f * (v0 + 0.044715f * v0 * v0 * v0);
                    float i1 = 0.7978845608028654f * (v1 + 0.044715f * v1 * v1 * v1);
                    v0 = 0.5f * v0 * (1.0f + tanhf(i0));
                    v1 = 0.5f * v1 * (1.0f + tanhf(i1));
                }
                *(float2*)(C + (size_t)rr * N + c) = make_float2(v0, v1);
            }
        }
    }
}

// ---------------------------------------------------------------------------
// Fused causal flash attention (fp32) — unchanged from passing round.
// ---------------------------------------------------------------------------
__global__ __launch_bounds__(256) void attn_kernel(const float* __restrict__ qkv,
                                                   float* __restrict__ out)
{
    const int TQ = 64, TK = 32, KS = DH_ + 1;
    __shared__ float Qs[TQ][DH_];
    __shared__ float KP[TK * KS];
    __shared__ float Vs[TK][DH_];

    int tid = threadIdx.x;
    int qt = blockIdx.x, head = blockIdx.y, batch = blockIdx.z;
    int qbase = qt * TQ;
    const float* base = qkv + (size_t)batch * S_ * D3_;
    int hd = head * DH_;

    #pragma unroll
    for (int t = 0; t < 4; t++) {
        int idx = tid + t * 256;
        int r = idx >> 4, d4 = (idx & 15) * 4;
        *(float4*)&Qs[r][d4] =
            *(const float4*)(base + (size_t)(qbase + r) * D3_ + hd + d4);
    }

    int tx = tid & 15, ty = tid >> 4;
    int r0 = ty * 4;
    int k0 = tx * 2;
    int d0 = tx * 4;

    float acc[4][4];
    float mrow[4], lrow[4];
    #pragma unroll
    for (int i = 0; i < 4; i++) {
        mrow[i] = -1e30f; lrow[i] = 0.f;
        #pragma unroll
        for (int j = 0; j < 4; j++) acc[i][j] = 0.f;
    }

    int ntiles = 2 * (qt + 1);
    for (int kt = 0; kt < ntiles; kt++) {
        int kbase = kt * TK;
        __syncthreads();

        #pragma unroll
        for (int t = 0; t < 2; t++) {
            int idx = tid + t * 256;
            int k = idx >> 4, d4 = (idx & 15) * 4;
            float4 kv = *(const float4*)(base + (size_t)(kbase + k) * D3_ + D_ + hd + d4);
            KP[k * KS + d4 + 0] = kv.x;
            KP[k * KS + d4 + 1] = kv.y;
            KP[k * KS + d4 + 2] = kv.z;
            KP[k * KS + d4 + 3] = kv.w;
            *(float4*)&Vs[k][d4] =
                *(const float4*)(base + (size_t)(kbase + k) * D3_ + 2 * D_ + hd + d4);
        }
        __syncthreads();

        float s[4][2] = {{0.f,0.f},{0.f,0.f},{0.f,0.f},{0.f,0.f}};
        #pragma unroll 8
        for (int d = 0; d < DH_; d++) {
            float kv0 = KP[(k0 + 0) * KS + d];
            float kv1 = KP[(k0 + 1) * KS + d];
            #pragma unroll
            for (int i = 0; i < 4; i++) {
                float qv = Qs[r0 + i][d];
                s[i][0] += qv * kv0;
                s[i][1] += qv * kv1;
            }
        }
        #pragma unroll
        for (int i = 0; i < 4; i++)
            #pragma unroll
            for (int j = 0; j < 2; j++) {
                int gq = qbase + r0 + i, gk = kbase + k0 + j;
                s[i][j] = (gk <= gq) ? s[i][j] * 0.125f : -1e30f;
            }

        float mnew[4], alpha[4];
        #pragma unroll
        for (int i = 0; i < 4; i++) {
            float mx = fmaxf(s[i][0], s[i][1]);
            #pragma unroll
            for (int o = 8; o > 0; o >>= 1)
                mx = fmaxf(mx, __shfl_xor_sync(0xffffffffu, mx, o));
            mnew[i]  = fmaxf(mrow[i], mx);
            alpha[i] = expf(mrow[i] - mnew[i]);
            mrow[i]  = mnew[i];
        }
        __syncthreads();

        #pragma unroll
        for (int i = 0; i < 4; i++) {
            float p0 = expf(s[i][0] - mnew[i]);
            float p1 = expf(s[i][1] - mnew[i]);
            KP[(r0 + i) * TK + k0 + 0] = p0;
            KP[(r0 + i) * TK + k0 + 1] = p1;
            float sum = p0 + p1;
            #pragma unroll
            for (int o = 8; o > 0; o >>= 1)
                sum += __shfl_xor_sync(0xffffffffu, sum, o);
            lrow[i] = lrow[i] * alpha[i] + sum;
            #pragma unroll
            for (int j = 0; j < 4; j++) acc[i][j] *= alpha[i];
        }
        __syncthreads();

        #pragma unroll 4
        for (int k = 0; k < TK; k++) {
            float4 v = *(const float4*)&Vs[k][d0];
            #pragma unroll
            for (int i = 0; i < 4; i++) {
                float p = KP[(r0 + i) * TK + k];
                acc[i][0] += p * v.x;
                acc[i][1] += p * v.y;
                acc[i][2] += p * v.z;
                acc[i][3] += p * v.w;
            }
        }
    }

    #pragma unroll
    for (int i = 0; i < 4; i++) {
        float inv = 1.0f / lrow[i];
        float4 o;
        o.x = acc[i][0] * inv; o.y = acc[i][1] * inv;
        o.z = acc[i][2] * inv; o.w = acc[i][3] * inv;
        *(float4*)(out + (size_t)(batch * S_ + qbase + r0 + i) * D_ + hd + d0) = o;
    }
}

// ---------------------------------------------------------------------------
// LayerNorm over D=768 per row; 256 threads, 3 elements each. (unchanged)
// ---------------------------------------------------------------------------
__global__ __launch_bounds__(256) void ln_kernel(const float* __restrict__ x,
                                                 const float* __restrict__ g,
                                                 const float* __restrict__ b,
                                                 float* __restrict__ out)
{
    int row = blockIdx.x;
    int tid = threadIdx.x;
    const float* xr = x + (size_t)row * D_;
    float v0 = xr[tid], v1 = xr[tid + 256], v2 = xr[tid + 512];

    __shared__ float red[8];
    float s = v0 + v1 + v2;
    #pragma unroll
    for (int o = 16; o > 0; o >>= 1) s += __shfl_xor_sync(~0u, s, o);
    if ((tid & 31) == 0) red[tid >> 5] = s;
    __syncthreads();
    float tot = 0.f;
    if (tid < 32) {
        tot = (tid < 8) ? red[tid] : 0.f;
        #pragma unroll
        for (int o = 4; o > 0; o >>= 1) tot += __shfl_xor_sync(~0u, tot, o);
        if (tid == 0) red[0] = tot;
    }
    __syncthreads();
    float mean = red[0] * (1.0f / D_);

    float d0 = v0 - mean, d1 = v1 - mean, d2 = v2 - mean;
    float q = d0 * d0 + d1 * d1 + d2 * d2;
    #pragma unroll
    for (int o = 16; o > 0; o >>= 1) q += __shfl_xor_sync(~0u, q, o);
    __syncthreads();
    if ((tid & 31) == 0) red[tid >> 5] = q;
    __syncthreads();
    if (tid < 32) {
        float t = (tid < 8) ? red[tid] : 0.f;
        #pragma unroll
        for (int o = 4; o > 0; o >>= 1) t += __shfl_xor_sync(~0u, t, o);
        if (tid == 0) red[0] = t;
    }
    __syncthreads();
    float rstd = rsqrtf(red[0] * (1.0f / D_) + 1e-5f);

    float* o = out + (size_t)row * D_;
    o[tid]       = d0 * rstd * g[tid]       + b[tid];
    o[tid + 256] = d1 * rstd * g[tid + 256] + b[tid + 256];
    o[tid + 512] = d2 * rstd * g[tid + 512] + b[tid + 512];
}

// ---------------------------------------------------------------------------
// Launch
// ---------------------------------------------------------------------------
extern "C" void kernel_launch(void* const* d_in, const int* in_sizes, int n_in,
                              void* d_out, int out_size)
{
    (void)in_sizes; (void)n_in; (void)out_size;

    const void*  x           = d_in[0];
    const float* we          = (const float*)d_in[1];
    const float* c_attn_w    = (const float*)d_in[2];
    const float* c_attn_b    = (const float*)d_in[3];
    const float* attn_proj_w = (const float*)d_in[4];
    const float* attn_proj_b = (const float*)d_in[5];
    const float* ln1_g       = (const float*)d_in[6];
    const float* ln1_b       = (const float*)d_in[7];
    const float* fc_w        = (const float*)d_in[8];
    const float* fc_b        = (const float*)d_in[9];
    const float* mlp_proj_w  = (const float*)d_in[10];
    const float* mlp_proj_b  = (const float*)d_in[11];
    const float* ln2_g       = (const float*)d_in[12];
    const float* ln2_b       = (const float*)d_in[13];
    float* out = (float*)d_out;

    float *qkv, *attnb, *r1, *nbuf, *ff, *r2;
    cudaGetSymbolAddress((void**)&qkv,   g_qkv);
    cudaGetSymbolAddress((void**)&attnb, g_attn);
    cudaGetSymbolAddress((void**)&r1,    g_r1);
    cudaGetSymbolAddress((void**)&nbuf,  g_n);
    cudaGetSymbolAddress((void**)&ff,    g_ff);
    cudaGetSymbolAddress((void**)&r2,    g_r2);

    // Opt-in to >48KB dynamic smem for all GEMM template instances.
    cudaFuncSetAttribute(mma_gemm_kernel<true, false, false>,
                         cudaFuncAttributeMaxDynamicSharedMemorySize, GEMM_SMEM_BYTES);
    cudaFuncSetAttribute(mma_gemm_kernel<true, true, false>,
                         cudaFuncAttributeMaxDynamicSharedMemorySize, GEMM_SMEM_BYTES);
    cudaFuncSetAttribute(mma_gemm_kernel<true, false, true>,
                         cudaFuncAttributeMaxDynamicSharedMemorySize, GEMM_SMEM_BYTES);

    embed_kernel<<<BS_, 256>>>(x, we, out);

    for (int l = 0; l < L_; l++) {
        const float* h    = out + (size_t)l * BS_ * D_;
        float*       hout = out + (size_t)(l + 1) * BS_ * D_;

        // qkv = h @ caw + cab
        mma_gemm_kernel<true, false, false>
            <<<dim3(D3_ / 128, BS_ / 128), 256, GEMM_SMEM_BYTES>>>(
            h, c_attn_w + (size_t)l * D_ * D3_, c_attn_b + (size_t)l * D3_,
            nullptr, qkv, BS_, D3_, D_);

        // a = causal_attention(qkv)
        attn_kernel<<<dim3(S_ / 64, H_, B_), 256>>>(qkv, attnb);

        // r1 = a @ apw + apb + h
        mma_gemm_kernel<true, true, false>
            <<<dim3(D_ / 128, BS_ / 128), 256, GEMM_SMEM_BYTES>>>(
            attnb, attn_proj_w + (size_t)l * D_ * D_, attn_proj_b + (size_t)l * D_,
            h, r1, BS_, D_, D_);

        // n = LN(r1)
        ln_kernel<<<BS_, 256>>>(r1, ln1_g + (size_t)l * D_, ln1_b + (size_t)l * D_, nbuf);

        // ff = gelu(n @ fw + fb)
        mma_gemm_kernel<true, false, true>
            <<<dim3(FF_ / 128, BS_ / 128), 256, GEMM_SMEM_BYTES>>>(
            nbuf, fc_w + (size_t)l * D_ * FF_, fc_b + (size_t)l * FF_,
            nullptr, ff, BS_, FF_, D_);

        // r2 = ff @ pw + pb + n
        mma_gemm_kernel<true, true, false>
            <<<dim3(D_ / 128, BS_ / 128), 256, GEMM_SMEM_BYTES>>>(
            ff, mlp_proj_w + (size_t)l * FF_ * D_, mlp_proj_b + (size_t)l * D_,
            nbuf, r2, BS_, D_, FF_);

        // out_{l+1} = LN(r2)
        ln_kernel<<<BS_, 256>>>(r2, ln2_g + (size_t)l * D_, ln2_b + (size_t)l * D_, hout);
    }
}

// round 5
// speedup vs baseline: 2.8881x; 1.0896x over previous
#include <cuda_runtime.h>
#include <math.h>
#include <stdint.h>

// Problem constants
#define B_     16
#define S_     512
#define D_     768
#define H_     12
#define DH_    64
#define L_     12
#define FF_    3072
#define VOCAB_ 40990
#define BS_    (B_ * S_)     // 8192 rows
#define D3_    (3 * D_)      // 2304

// ---------------------------------------------------------------------------
// Scratch (static device globals: allocation-free, graph-capturable)
// ---------------------------------------------------------------------------
__device__ float g_qkv[(size_t)BS_ * D3_];
__device__ float g_attn[(size_t)BS_ * D_];
__device__ float g_r1[(size_t)BS_ * D_];
__device__ float g_n[(size_t)BS_ * D_];
__device__ float g_ff[(size_t)BS_ * FF_];
__device__ float g_r2[(size_t)BS_ * D_];
// Transposed ([N,K]) weight copies, pre-rounded to tf32
__device__ float g_caw_t[(size_t)L_ * D3_ * D_];
__device__ float g_apw_t[(size_t)L_ * D_ * D_];
__device__ float g_fcw_t[(size_t)L_ * FF_ * D_];
__device__ float g_mpw_t[(size_t)L_ * D_ * FF_];

// ---------------------------------------------------------------------------
// Helpers
// ---------------------------------------------------------------------------
__device__ __forceinline__ uint32_t smem_u32(const void* p) {
    uint32_t a;
    asm("{ .reg .u64 t; cvta.to.shared.u64 t, %1; cvt.u32.u64 %0, t; }"
        : "=r"(a) : "l"(p));
    return a;
}
__device__ __forceinline__ unsigned f2tf(float f) {
    unsigned r;
    asm("cvt.rna.tf32.f32 %0, %1;" : "=r"(r) : "f"(f));
    return r;
}
__device__ __forceinline__ void mma_tf32(float c[4], const unsigned a[4],
                                         const unsigned b[2]) {
    asm volatile(
        "mma.sync.aligned.m16n8k8.row.col.f32.tf32.tf32.f32 "
        "{%0,%1,%2,%3},{%4,%5,%6,%7},{%8,%9},{%0,%1,%2,%3};"
        : "+f"(c[0]), "+f"(c[1]), "+f"(c[2]), "+f"(c[3])
        : "r"(a[0]), "r"(a[1]), "r"(a[2]), "r"(a[3]), "r"(b[0]), "r"(b[1]));
}
__device__ __forceinline__ void cp16(unsigned smem_addr, const float* gptr) {
    asm volatile("cp.async.cg.shared.global [%0], [%1], 16;\n"
                 :: "r"(smem_addr), "l"(gptr));
}
#define LDSM4(r0, r1, r2, r3, addr) \
    asm volatile("ldmatrix.sync.aligned.m8n8.x4.shared.b16 {%0,%1,%2,%3}, [%4];" \
        : "=r"(r0), "=r"(r1), "=r"(r2), "=r"(r3) : "r"(addr))

// ---------------------------------------------------------------------------
// Embedding: out[t] = we[x[t,0]] + we[x[t,1]]  (x int32 or int64, detected)
// ---------------------------------------------------------------------------
__global__ void embed_kernel(const void* __restrict__ x,
                             const float* __restrict__ we,
                             float* __restrict__ out)
{
    __shared__ int is64;
    int t = blockIdx.x;
    if (threadIdx.x == 0) {
        const unsigned long long* p = (const unsigned long long*)x;
        int ok = 1;
        #pragma unroll 1
        for (int i = 0; i < 64; i++)
            if (p[i] >= (unsigned long long)VOCAB_) { ok = 0; break; }
        is64 = ok;
    }
    __syncthreads();
    long long i0, i1;
    if (is64) {
        const long long* p = (const long long*)x;
        i0 = p[2 * t]; i1 = p[2 * t + 1];
    } else {
        const int* p = (const int*)x;
        i0 = p[2 * t]; i1 = p[2 * t + 1];
    }
    const float* w0 = we + (size_t)i0 * D_;
    const float* w1 = we + (size_t)i1 * D_;
    float* o = out + (size_t)t * D_;
    for (int c = threadIdx.x; c < D_; c += blockDim.x)
        o[c] = w0[c] + w1[c];
}

// ---------------------------------------------------------------------------
// Weight transpose + tf32 pre-round: Wt[l][n][k] = tf32(W[l][k][n])
// ---------------------------------------------------------------------------
__global__ void transpose_kernel(const float* __restrict__ W,
                                 float* __restrict__ Wt, int K, int N)
{
    __shared__ float t[32][33];
    const float* Wl = W + (size_t)blockIdx.z * K * N;
    float* Wtl = Wt + (size_t)blockIdx.z * K * N;
    int nb = blockIdx.x * 32, kb = blockIdx.y * 32;
    int tx = threadIdx.x, ty = threadIdx.y;
    #pragma unroll
    for (int j = 0; j < 32; j += 8)
        t[ty + j][tx] = Wl[(size_t)(kb + ty + j) * N + nb + tx];
    __syncthreads();
    #pragma unroll
    for (int j = 0; j < 32; j += 8)
        Wtl[(size_t)(nb + ty + j) * K + kb + tx] =
            __uint_as_float(f2tf(t[tx][ty + j]));
}

// ---------------------------------------------------------------------------
// TF32 MMA GEMM, ldmatrix fragments, 3-stage cp.async pipeline.
// C[M,N] = A[M,K] @ Bt[N,K]^T (+bias)(+res)(gelu)(round-out)
// Both operands K-major in SMEM: [128 rows][32 k], row stride 36 floats.
// Tile 128x128x32, 256 threads (8 warps), warp tile 32x64.
// M%128==0, N%128==0, K%64==0 (NK>=2), 16B-aligned pointers.
// Bt must be pre-rounded to tf32. A rounded on consume iff CVTA.
// ---------------------------------------------------------------------------
#define OPF    (128 * 36)           // floats per operand per stage
#define STGF   (2 * OPF)            // floats per stage (A then B)
#define NSTG   3
#define GEMM_SMEM (NSTG * STGF * 4) // 110592 bytes

template<bool BIAS, bool RES, bool DOGELU, bool CVTA, bool RNDOUT>
__global__ __launch_bounds__(256, 2) void mma_gemm_kernel(
    const float* __restrict__ A, const float* __restrict__ Bt,
    const float* __restrict__ bias, const float* __restrict__ res,
    float* __restrict__ C, int M, int N, int K)
{
    extern __shared__ float smem[];
    const int tid  = threadIdx.x;
    const int lane = tid & 31;
    const int wid  = tid >> 5;
    const int gid  = lane >> 2;   // 0..7
    const int tig  = lane & 3;    // 0..3
    const int warp_m = wid >> 1;  // 0..3
    const int warp_n = wid & 1;   // 0..1
    const int bm = blockIdx.y * 128, bn = blockIdx.x * 128;

    const float* Arow = A + (size_t)bm * K;
    const float* Brow = Bt + (size_t)bn * K;

    // Fill indices: each thread copies 16B per row-group; 4 groups per operand.
    const int frow = tid >> 3;        // 0..31 (+h*32)
    const int fcol = (tid & 7) * 4;   // 0..28

    auto load_stage = [&](int s, int ic) {
        float* As = smem + s * STGF;
        float* Bs = As + OPF;
        const int k0 = ic << 5;
        #pragma unroll
        for (int h = 0; h < 4; h++) {
            int r = h * 32 + frow;
            cp16((unsigned)__cvta_generic_to_shared(&As[r * 36 + fcol]),
                 Arow + (size_t)r * K + k0 + fcol);
        }
        #pragma unroll
        for (int h = 0; h < 4; h++) {
            int r = h * 32 + frow;
            cp16((unsigned)__cvta_generic_to_shared(&Bs[r * 36 + fcol]),
                 Brow + (size_t)r * K + k0 + fcol);
        }
        asm volatile("cp.async.commit_group;" ::: "memory");
    };

    float acc[2][8][4];
    #pragma unroll
    for (int i = 0; i < 2; i++)
        #pragma unroll
        for (int j = 0; j < 8; j++)
            #pragma unroll
            for (int c = 0; c < 4; c++) acc[i][j][c] = 0.f;

    // ldmatrix per-thread byte offsets (within operand buffer)
    const uint32_t sbase = smem_u32(smem);
    const uint32_t aoff =
        ((warp_m * 32 + (lane & 15)) * 36 + ((lane >> 4) << 2)) * 4;
    const uint32_t boff =
        ((warp_n * 64 + (lane & 7) + ((lane >> 4) << 3)) * 36
         + (((lane >> 3) & 1) << 2)) * 4;

    const int NK = K >> 5;
    load_stage(0, 0);
    load_stage(1, 1);

    for (int it = 0; it < NK; it++) {
        if (it + 1 < NK)
            asm volatile("cp.async.wait_group 1;" ::: "memory");
        else
            asm volatile("cp.async.wait_group 0;" ::: "memory");
        __syncthreads();
        if (it + 2 < NK) load_stage((it + 2) % NSTG, it + 2);

        const uint32_t sA = sbase + (uint32_t)((it % NSTG) * STGF) * 4u;
        const uint32_t sB = sA + OPF * 4u;

        #pragma unroll
        for (int ks = 0; ks < 4; ks++) {
            const uint32_t kb = ks * 32;   // 8 floats = 32 bytes
            unsigned a[2][4];
            LDSM4(a[0][0], a[0][1], a[0][2], a[0][3], sA + aoff + kb);
            LDSM4(a[1][0], a[1][1], a[1][2], a[1][3],
                  sA + aoff + 16u * 36u * 4u + kb);
            if (CVTA) {
                #pragma unroll
                for (int im = 0; im < 2; im++)
                    #pragma unroll
                    for (int q = 0; q < 4; q++)
                        a[im][q] = f2tf(__uint_as_float(a[im][q]));
            }
            unsigned b[8][2];
            #pragma unroll
            for (int q = 0; q < 4; q++)
                LDSM4(b[2 * q][0], b[2 * q][1], b[2 * q + 1][0], b[2 * q + 1][1],
                      sB + boff + (uint32_t)(q * 16 * 36 * 4) + kb);
            #pragma unroll
            for (int im = 0; im < 2; im++)
                #pragma unroll
                for (int j = 0; j < 8; j++)
                    mma_tf32(acc[im][j], a[im], b[j]);
        }
    }

    // Epilogue
    #pragma unroll
    for (int im = 0; im < 2; im++) {
        #pragma unroll
        for (int j = 0; j < 8; j++) {
            int r = bm + warp_m * 32 + im * 16 + gid;
            int c = bn + warp_n * 64 + j * 8 + tig * 2;
            #pragma unroll
            for (int half = 0; half < 2; half++) {
                int rr = r + half * 8;
                float v0 = acc[im][j][half * 2 + 0];
                float v1 = acc[im][j][half * 2 + 1];
                if (BIAS) { v0 += bias[c]; v1 += bias[c + 1]; }
                if (RES) {
                    const float* rp = res + (size_t)rr * N + c;
                    v0 += rp[0]; v1 += rp[1];
                }
                if (DOGELU) {
                    float i0 = 0.7978845608028654f * (v0 + 0.044715f * v0 * v0 * v0);
                    float i1 = 0.7978845608028654f * (v1 + 0.044715f * v1 * v1 * v1);
                    v0 = 0.5f * v0 * (1.0f + tanhf(i0));
                    v1 = 0.5f * v1 * (1.0f + tanhf(i1));
                }
                if (RNDOUT) {
                    v0 = __uint_as_float(f2tf(v0));
                    v1 = __uint_as_float(f2tf(v1));
                }
                *(float2*)(C + (size_t)rr * N + c) = make_float2(v0, v1);
            }
        }
    }
}

// ---------------------------------------------------------------------------
// Fused causal flash attention (fp32). Output pre-rounded to tf32
// (it feeds only the proj GEMM's A operand, which skips cvt).
// ---------------------------------------------------------------------------
__global__ __launch_bounds__(256) void attn_kernel(const float* __restrict__ qkv,
                                                   float* __restrict__ out)
{
    const int TQ = 64, TK = 32, KS = DH_ + 1;
    __shared__ float Qs[TQ][DH_];
    __shared__ float KP[TK * KS];
    __shared__ float Vs[TK][DH_];

    int tid = threadIdx.x;
    int qt = blockIdx.x, head = blockIdx.y, batch = blockIdx.z;
    int qbase = qt * TQ;
    const float* base = qkv + (size_t)batch * S_ * D3_;
    int hd = head * DH_;

    #pragma unroll
    for (int t = 0; t < 4; t++) {
        int idx = tid + t * 256;
        int r = idx >> 4, d4 = (idx & 15) * 4;
        *(float4*)&Qs[r][d4] =
            *(const float4*)(base + (size_t)(qbase + r) * D3_ + hd + d4);
    }

    int tx = tid & 15, ty = tid >> 4;
    int r0 = ty * 4;
    int k0 = tx * 2;
    int d0 = tx * 4;

    float acc[4][4];
    float mrow[4], lrow[4];
    #pragma unroll
    for (int i = 0; i < 4; i++) {
        mrow[i] = -1e30f; lrow[i] = 0.f;
        #pragma unroll
        for (int j = 0; j < 4; j++) acc[i][j] = 0.f;
    }

    int ntiles = 2 * (qt + 1);
    for (int kt = 0; kt < ntiles; kt++) {
        int kbase = kt * TK;
        __syncthreads();

        #pragma unroll
        for (int t = 0; t < 2; t++) {
            int idx = tid + t * 256;
            int k = idx >> 4, d4 = (idx & 15) * 4;
            float4 kv = *(const float4*)(base + (size_t)(kbase + k) * D3_ + D_ + hd + d4);
            KP[k * KS + d4 + 0] = kv.x;
            KP[k * KS + d4 + 1] = kv.y;
            KP[k * KS + d4 + 2] = kv.z;
            KP[k * KS + d4 + 3] = kv.w;
            *(float4*)&Vs[k][d4] =
                *(const float4*)(base + (size_t)(kbase + k) * D3_ + 2 * D_ + hd + d4);
        }
        __syncthreads();

        float s[4][2] = {{0.f,0.f},{0.f,0.f},{0.f,0.f},{0.f,0.f}};
        #pragma unroll 8
        for (int d = 0; d < DH_; d++) {
            float kv0 = KP[(k0 + 0) * KS + d];
            float kv1 = KP[(k0 + 1) * KS + d];
            #pragma unroll
            for (int i = 0; i < 4; i++) {
                float qv = Qs[r0 + i][d];
                s[i][0] += qv * kv0;
                s[i][1] += qv * kv1;
            }
        }
        #pragma unroll
        for (int i = 0; i < 4; i++)
            #pragma unroll
            for (int j = 0; j < 2; j++) {
                int gq = qbase + r0 + i, gk = kbase + k0 + j;
                s[i][j] = (gk <= gq) ? s[i][j] * 0.125f : -1e30f;
            }

        float mnew[4], alpha[4];
        #pragma unroll
        for (int i = 0; i < 4; i++) {
            float mx = fmaxf(s[i][0], s[i][1]);
            #pragma unroll
            for (int o = 8; o > 0; o >>= 1)
                mx = fmaxf(mx, __shfl_xor_sync(0xffffffffu, mx, o));
            mnew[i]  = fmaxf(mrow[i], mx);
            alpha[i] = expf(mrow[i] - mnew[i]);
            mrow[i]  = mnew[i];
        }
        __syncthreads();

        #pragma unroll
        for (int i = 0; i < 4; i++) {
            float p0 = expf(s[i][0] - mnew[i]);
            float p1 = expf(s[i][1] - mnew[i]);
            KP[(r0 + i) * TK + k0 + 0] = p0;
            KP[(r0 + i) * TK + k0 + 1] = p1;
            float sum = p0 + p1;
            #pragma unroll
            for (int o = 8; o > 0; o >>= 1)
                sum += __shfl_xor_sync(0xffffffffu, sum, o);
            lrow[i] = lrow[i] * alpha[i] + sum;
            #pragma unroll
            for (int j = 0; j < 4; j++) acc[i][j] *= alpha[i];
        }
        __syncthreads();

        #pragma unroll 4
        for (int k = 0; k < TK; k++) {
            float4 v = *(const float4*)&Vs[k][d0];
            #pragma unroll
            for (int i = 0; i < 4; i++) {
                float p = KP[(r0 + i) * TK + k];
                acc[i][0] += p * v.x;
                acc[i][1] += p * v.y;
                acc[i][2] += p * v.z;
                acc[i][3] += p * v.w;
            }
        }
    }

    #pragma unroll
    for (int i = 0; i < 4; i++) {
        float inv = 1.0f / lrow[i];
        float4 o;
        o.x = __uint_as_float(f2tf(acc[i][0] * inv));
        o.y = __uint_as_float(f2tf(acc[i][1] * inv));
        o.z = __uint_as_float(f2tf(acc[i][2] * inv));
        o.w = __uint_as_float(f2tf(acc[i][3] * inv));
        *(float4*)(out + (size_t)(batch * S_ + qbase + r0 + i) * D_ + hd + d0) = o;
    }
}

// ---------------------------------------------------------------------------
// LayerNorm over D=768 per row (unchanged)
// ---------------------------------------------------------------------------
__global__ __launch_bounds__(256) void ln_kernel(const float* __restrict__ x,
                                                 const float* __restrict__ g,
                                                 const float* __restrict__ b,
                                                 float* __restrict__ out)
{
    int row = blockIdx.x;
    int tid = threadIdx.x;
    const float* xr = x + (size_t)row * D_;
    float v0 = xr[tid], v1 = xr[tid + 256], v2 = xr[tid + 512];

    __shared__ float red[8];
    float s = v0 + v1 + v2;
    #pragma unroll
    for (int o = 16; o > 0; o >>= 1) s += __shfl_xor_sync(~0u, s, o);
    if ((tid & 31) == 0) red[tid >> 5] = s;
    __syncthreads();
    float tot = 0.f;
    if (tid < 32) {
        tot = (tid < 8) ? red[tid] : 0.f;
        #pragma unroll
        for (int o = 4; o > 0; o >>= 1) tot += __shfl_xor_sync(~0u, tot, o);
        if (tid == 0) red[0] = tot;
    }
    __syncthreads();
    float mean = red[0] * (1.0f / D_);

    float d0 = v0 - mean, d1 = v1 - mean, d2 = v2 - mean;
    float q = d0 * d0 + d1 * d1 + d2 * d2;
    #pragma unroll
    for (int o = 16; o > 0; o >>= 1) q += __shfl_xor_sync(~0u, q, o);
    __syncthreads();
    if ((tid & 31) == 0) red[tid >> 5] = q;
    __syncthreads();
    if (tid < 32) {
        float t = (tid < 8) ? red[tid] : 0.f;
        #pragma unroll
        for (int o = 4; o > 0; o >>= 1) t += __shfl_xor_sync(~0u, t, o);
        if (tid == 0) red[0] = t;
    }
    __syncthreads();
    float rstd = rsqrtf(red[0] * (1.0f / D_) + 1e-5f);

    float* o = out + (size_t)row * D_;
    o[tid]       = d0 * rstd * g[tid]       + b[tid];
    o[tid + 256] = d1 * rstd * g[tid + 256] + b[tid + 256];
    o[tid + 512] = d2 * rstd * g[tid + 512] + b[tid + 512];
}

// ---------------------------------------------------------------------------
// Launch
// ---------------------------------------------------------------------------
extern "C" void kernel_launch(void* const* d_in, const int* in_sizes, int n_in,
                              void* d_out, int out_size)
{
    (void)in_sizes; (void)n_in; (void)out_size;

    const void*  x           = d_in[0];
    const float* we          = (const float*)d_in[1];
    const float* c_attn_w    = (const float*)d_in[2];
    const float* c_attn_b    = (const float*)d_in[3];
    const float* attn_proj_w = (const float*)d_in[4];
    const float* attn_proj_b = (const float*)d_in[5];
    const float* ln1_g       = (const float*)d_in[6];
    const float* ln1_b       = (const float*)d_in[7];
    const float* fc_w        = (const float*)d_in[8];
    const float* fc_b        = (const float*)d_in[9];
    const float* mlp_proj_w  = (const float*)d_in[10];
    const float* mlp_proj_b  = (const float*)d_in[11];
    const float* ln2_g       = (const float*)d_in[12];
    const float* ln2_b       = (const float*)d_in[13];
    float* out = (float*)d_out;

    float *qkv, *attnb, *r1, *nbuf, *ff, *r2;
    float *cawT, *apwT, *fcwT, *mpwT;
    cudaGetSymbolAddress((void**)&qkv,   g_qkv);
    cudaGetSymbolAddress((void**)&attnb, g_attn);
    cudaGetSymbolAddress((void**)&r1,    g_r1);
    cudaGetSymbolAddress((void**)&nbuf,  g_n);
    cudaGetSymbolAddress((void**)&ff,    g_ff);
    cudaGetSymbolAddress((void**)&r2,    g_r2);
    cudaGetSymbolAddress((void**)&cawT,  g_caw_t);
    cudaGetSymbolAddress((void**)&apwT,  g_apw_t);
    cudaGetSymbolAddress((void**)&fcwT,  g_fcw_t);
    cudaGetSymbolAddress((void**)&mpwT,  g_mpw_t);

    // GEMM variants:
    //   qkv: bias, CVTA (A=h full fp32)
    //   proj/mlp: bias+res, A pre-rounded (attnb / ff)
    //   fc: bias+gelu, CVTA (A=nbuf), round output (feeds mlp A)
    cudaFuncSetAttribute(mma_gemm_kernel<true, false, false, true, false>,
                         cudaFuncAttributeMaxDynamicSharedMemorySize, GEMM_SMEM);
    cudaFuncSetAttribute(mma_gemm_kernel<true, true, false, false, false>,
                         cudaFuncAttributeMaxDynamicSharedMemorySize, GEMM_SMEM);
    cudaFuncSetAttribute(mma_gemm_kernel<true, false, true, true, true>,
                         cudaFuncAttributeMaxDynamicSharedMemorySize, GEMM_SMEM);

    // One-time weight transposes (+tf32 pre-round) -> [N,K]
    transpose_kernel<<<dim3(D3_ / 32, D_ / 32, L_), dim3(32, 8)>>>(c_attn_w, cawT, D_, D3_);
    transpose_kernel<<<dim3(D_ / 32, D_ / 32, L_), dim3(32, 8)>>>(attn_proj_w, apwT, D_, D_);
    transpose_kernel<<<dim3(FF_ / 32, D_ / 32, L_), dim3(32, 8)>>>(fc_w, fcwT, D_, FF_);
    transpose_kernel<<<dim3(D_ / 32, FF_ / 32, L_), dim3(32, 8)>>>(mlp_proj_w, mpwT, FF_, D_);

    embed_kernel<<<BS_, 256>>>(x, we, out);

    for (int l = 0; l < L_; l++) {
        const float* h    = out + (size_t)l * BS_ * D_;
        float*       hout = out + (size_t)(l + 1) * BS_ * D_;

        // qkv = h @ caw + cab
        mma_gemm_kernel<true, false, false, true, false>
            <<<dim3(D3_ / 128, BS_ / 128), 256, GEMM_SMEM>>>(
            h, cawT + (size_t)l * D3_ * D_, c_attn_b + (size_t)l * D3_,
            nullptr, qkv, BS_, D3_, D_);

        // a = causal_attention(qkv)  (tf32-rounded output)
        attn_kernel<<<dim3(S_ / 64, H_, B_), 256>>>(qkv, attnb);

        // r1 = a @ apw + apb + h
        mma_gemm_kernel<true, true, false, false, false>
            <<<dim3(D_ / 128, BS_ / 128), 256, GEMM_SMEM>>>(
            attnb, apwT + (size_t)l * D_ * D_, attn_proj_b + (size_t)l * D_,
            h, r1, BS_, D_, D_);

        // n = LN(r1)
        ln_kernel<<<BS_, 256>>>(r1, ln1_g + (size_t)l * D_, ln1_b + (size_t)l * D_, nbuf);

        // ff = gelu(n @ fw + fb)  (tf32-rounded output)
        mma_gemm_kernel<true, false, true, true, true>
            <<<dim3(FF_ / 128, BS_ / 128), 256, GEMM_SMEM>>>(
            nbuf, fcwT + (size_t)l * FF_ * D_, fc_b + (size_t)l * FF_,
            nullptr, ff, BS_, FF_, D_);

        // r2 = ff @ pw + pb + n
        mma_gemm_kernel<true, true, false, false, false>
            <<<dim3(D_ / 128, BS_ / 128), 256, GEMM_SMEM>>>(
            ff, mpwT + (size_t)l * D_ * FF_, mlp_proj_b + (size_t)l * D_,
            nbuf, r2, BS_, D_, FF_);

        // out_{l+1} = LN(r2)
        ln_kernel<<<BS_, 256>>>(r2, ln2_g + (size_t)l * D_, ln2_b + (size_t)l * D_, hout);
    }
}